// round 1
// baseline (speedup 1.0000x reference)
#include <cuda_runtime.h>

#define GROUPS 8
#define ICPG 16
#define OCPG 16
#define HIN 256
#define WIN 256
#define NB 4
#define CIN 128
#define HOUT 512
#define WOUT 512
#define TILE_H 64
#define TILE_W 32
#define THREADS 512
#define XS_ROWS (TILE_H + 2)   // 66
#define XS_COLS (TILE_W + 2)   // 34
#define XS_STRIDE 36           // pad to mult of 4 for LDS.128 alignment

typedef unsigned long long ull;

// Effective phase filters: [g][op(8)][ic(16)][tap(9)][oi(2)] as float4 =
// (py0px0, py0px1, py1px0, py1px1) for oc = g*16 + op*2 + oi
__device__ float4 g_weff[GROUPS * 8 * ICPG * 9 * 2];

__device__ __forceinline__ ull pack2(float v) {
    ull r; asm("mov.b64 %0, {%1, %1};" : "=l"(r) : "f"(v)); return r;
}
__device__ __forceinline__ void fma2(ull &acc, ull a, ull b) {
    asm("fma.rn.f32x2 %0, %1, %2, %0;" : "+l"(acc) : "l"(a), "l"(b));
}

// Build Weff[p][r][oc][ic][ky][kx] = sum_{kh,kw} w[oc,ic,kh,kw]*A[p][kh][ky]*A[r][kw][kx]
// with A[p][kh][d] = g[2d+1-p-kh] (if in [0,3]), g[a] = 2*f[3-a].
__global__ void prep_weff(const float* __restrict__ f, const float* __restrict__ w) {
    int idx = blockIdx.x * blockDim.x + threadIdx.x;
    if (idx >= GROUPS * 8 * ICPG * 9 * 2) return;
    int oi = idx & 1;
    int t  = (idx >> 1) % 9;
    int ic = (idx / 18) % ICPG;
    int ocp = idx / (18 * ICPG);      // g*8 + op
    int g = ocp >> 3, op = ocp & 7;
    int oc = g * OCPG + op * 2 + oi;
    int ky = t / 3, kx = t % 3;
    float gf[4];
#pragma unroll
    for (int a = 0; a < 4; ++a) gf[a] = 2.0f * f[3 - a];
    float4 res = make_float4(0.f, 0.f, 0.f, 0.f);
#pragma unroll
    for (int kh = 0; kh < 3; ++kh) {
        int ay0i = 2 * ky + 1 - 0 - kh;
        int ay1i = 2 * ky + 1 - 1 - kh;
        float Ay0 = (ay0i >= 0 && ay0i < 4) ? gf[ay0i] : 0.f;
        float Ay1 = (ay1i >= 0 && ay1i < 4) ? gf[ay1i] : 0.f;
#pragma unroll
        for (int kw = 0; kw < 3; ++kw) {
            int ax0i = 2 * kx + 1 - 0 - kw;
            int ax1i = 2 * kx + 1 - 1 - kw;
            float Ax0 = (ax0i >= 0 && ax0i < 4) ? gf[ax0i] : 0.f;
            float Ax1 = (ax1i >= 0 && ax1i < 4) ? gf[ax1i] : 0.f;
            float wv = w[((oc * ICPG + ic) * 3 + kh) * 3 + kw];
            res.x += wv * Ay0 * Ax0;
            res.y += wv * Ay0 * Ax1;
            res.z += wv * Ay1 * Ax0;
            res.w += wv * Ay1 * Ax1;
        }
    }
    g_weff[idx] = res;
}

__global__ __launch_bounds__(THREADS, 1)
void conv_up_kernel(const float* __restrict__ x, float* __restrict__ out) {
    extern __shared__ float smem[];
    float4* wsm4 = (float4*)smem;                       // 2304 float4 = 36864 B
    float* xs = smem + 8 * ICPG * 9 * 2 * 4;            // offset 9216 floats

    const int tile = blockIdx.x;                        // 0..31
    const int g = blockIdx.y;
    const int n = blockIdx.z;
    const int tid = threadIdx.x;
    const int q0 = (tile & 7) * TILE_W;
    const int m0 = (tile >> 3) * TILE_H;

    // stage this group's phase filters
    const float4* gw = g_weff + g * (8 * ICPG * 9 * 2);
    for (int i = tid; i < 8 * ICPG * 9 * 2; i += THREADS) wsm4[i] = gw[i];

    // stage x tile (all 16 ic) with zero halo
    const float* xg = x + ((size_t)(n * CIN + g * ICPG)) * (HIN * WIN);
    for (int idx = tid; idx < ICPG * XS_ROWS * XS_COLS; idx += THREADS) {
        int c = idx % XS_COLS;
        int r = (idx / XS_COLS) % XS_ROWS;
        int ic = idx / (XS_COLS * XS_ROWS);
        int gm = m0 + r - 1, gq = q0 + c - 1;
        float v = 0.f;
        if (gm >= 0 && gm < HIN && gq >= 0 && gq < WIN)
            v = xg[(size_t)ic * (HIN * WIN) + gm * WIN + gq];
        xs[(ic * XS_ROWS + r) * XS_STRIDE + c] = v;
    }
    __syncthreads();

    const int txl = tid & 7, tyl = tid >> 3;            // tyl 0..63
    const int qc = txl * 4;
    const int gm = m0 + tyl;
    const int gq = q0 + qc;
    float* outg = out + (((size_t)n * CIN + g * OCPG) * HOUT) * WOUT;

    for (int op = 0; op < 8; ++op) {
        ull acc[2][2][4];                               // [oi][py][col], f32x2 over px
#pragma unroll
        for (int i = 0; i < 2; ++i)
#pragma unroll
            for (int j = 0; j < 2; ++j)
#pragma unroll
                for (int c = 0; c < 4; ++c) acc[i][j][c] = 0ull;

        const ulonglong2* wrow = (const ulonglong2*)(wsm4 + op * (ICPG * 9 * 2));
#pragma unroll 1
        for (int ic = 0; ic < ICPG; ++ic) {
            const float* xr = xs + (ic * XS_ROWS + tyl) * XS_STRIDE + qc;
            ull xp[3][6];
#pragma unroll
            for (int ky = 0; ky < 3; ++ky) {
                float4 v4 = *(const float4*)(xr + ky * XS_STRIDE);
                float2 v2 = *(const float2*)(xr + ky * XS_STRIDE + 4);
                xp[ky][0] = pack2(v4.x); xp[ky][1] = pack2(v4.y);
                xp[ky][2] = pack2(v4.z); xp[ky][3] = pack2(v4.w);
                xp[ky][4] = pack2(v2.x); xp[ky][5] = pack2(v2.y);
            }
            const ulonglong2* wp = wrow + ic * 18;
#pragma unroll
            for (int t = 0; t < 9; ++t) {
                const int ky = t / 3, kx = t % 3;
                ulonglong2 w0 = wp[t * 2 + 0];          // oi=0: lo=py0 pair, hi=py1 pair
                ulonglong2 w1 = wp[t * 2 + 1];          // oi=1
#pragma unroll
                for (int c = 0; c < 4; ++c) {
                    ull xv = xp[ky][kx + c];
                    fma2(acc[0][0][c], w0.x, xv);
                    fma2(acc[0][1][c], w0.y, xv);
                    fma2(acc[1][0][c], w1.x, xv);
                    fma2(acc[1][1][c], w1.y, xv);
                }
            }
        }
        // store 2 oc × 2 rows × 8 contiguous floats
#pragma unroll
        for (int oi = 0; oi < 2; ++oi) {
            int oc = op * 2 + oi;
            float* obase = outg + ((size_t)oc * HOUT + 2 * gm) * WOUT + 2 * gq;
#pragma unroll
            for (int py = 0; py < 2; ++py) {
                float2 a0 = *(float2*)&acc[oi][py][0];
                float2 a1 = *(float2*)&acc[oi][py][1];
                float2 a2 = *(float2*)&acc[oi][py][2];
                float2 a3 = *(float2*)&acc[oi][py][3];
                float4 v0 = make_float4(a0.x, a0.y, a1.x, a1.y);
                float4 v1 = make_float4(a2.x, a2.y, a3.x, a3.y);
                float* p = obase + py * WOUT;
                *(float4*)(p) = v0;
                *(float4*)(p + 4) = v1;
            }
        }
    }
}

extern "C" void kernel_launch(void* const* d_in, const int* in_sizes, int n_in,
                              void* d_out, int out_size) {
    const float* x = (const float*)d_in[0];
    const float* f = (const float*)d_in[1];
    const float* w = (const float*)d_in[2];
    float* out = (float*)d_out;

    // phase-filter prep: 18432 float4 entries
    prep_weff<<<72, 256>>>(f, w);

    const int smem_bytes = (8 * ICPG * 9 * 2 * 4 + ICPG * XS_ROWS * XS_STRIDE) * 4; // 188928
    cudaFuncSetAttribute(conv_up_kernel, cudaFuncAttributeMaxDynamicSharedMemorySize, smem_bytes);

    dim3 grid((WIN / TILE_W) * (HIN / TILE_H), GROUPS, NB); // (32, 8, 4)
    conv_up_kernel<<<grid, THREADS, smem_bytes>>>(x, out);
}